// round 7
// baseline (speedup 1.0000x reference)
#include <cuda_runtime.h>
#include <cuda_fp16.h>
#include <math.h>
#include <stdint.h>

#define B_    2
#define S_    2048
#define DIM_  1024
#define H_    16
#define HD_   64
#define FFN_  4096
#define NTOK  (B_*S_)

// ----------------------------------------------------------------------
// Scratch buffers (device globals; no allocation anywhere)
// ----------------------------------------------------------------------
__device__ __half g_h16[NTOK*DIM_];
__device__ __half g_qkv16[NTOK*3*DIM_];
__device__ __half g_q16[NTOK*DIM_];
__device__ __half g_k16[NTOK*DIM_];
__device__ __half g_v16[NTOK*DIM_];
__device__ __half g_ctx16[NTOK*DIM_];
__device__ float  g_x1[NTOK*DIM_];
__device__ __half g_mid16[NTOK*FFN_];
// transposed fp16 weights, [N, K] layout
__device__ __half g_qkvwT[3*DIM_*DIM_];
__device__ __half g_outwT[DIM_*DIM_];
__device__ __half g_w1T[FFN_*DIM_];
__device__ __half g_w2T[DIM_*FFN_];

// ----------------------------------------------------------------------
// PTX helpers
// ----------------------------------------------------------------------
__device__ __forceinline__ void ldsm4(uint32_t* r, uint32_t addr)
{
    asm volatile("ldmatrix.sync.aligned.m8n8.x4.shared.b16 {%0,%1,%2,%3}, [%4];"
        : "=r"(r[0]), "=r"(r[1]), "=r"(r[2]), "=r"(r[3]) : "r"(addr));
}

__device__ __forceinline__ void ldsm2t(uint32_t* r, uint32_t addr)
{
    asm volatile("ldmatrix.sync.aligned.m8n8.x2.trans.shared.b16 {%0,%1}, [%2];"
        : "=r"(r[0]), "=r"(r[1]) : "r"(addr));
}

__device__ __forceinline__ void mma16816(float* c, const uint32_t* a, const uint32_t* b)
{
    asm volatile("mma.sync.aligned.m16n8k16.row.col.f32.f16.f16.f32 "
        "{%0,%1,%2,%3}, {%4,%5,%6,%7}, {%8,%9}, {%0,%1,%2,%3};"
        : "+f"(c[0]), "+f"(c[1]), "+f"(c[2]), "+f"(c[3])
        : "r"(a[0]), "r"(a[1]), "r"(a[2]), "r"(a[3]), "r"(b[0]), "r"(b[1]));
}

__device__ __forceinline__ void cpa16(uint32_t dst, const void* src)
{
    asm volatile("cp.async.cg.shared.global [%0], [%1], 16;" :: "r"(dst), "l"(src));
}

__device__ __forceinline__ void cpa_commit()
{
    asm volatile("cp.async.commit_group;");
}

__device__ __forceinline__ void cpa_wait0()
{
    asm volatile("cp.async.wait_group 0;");
}

__device__ __forceinline__ void cpa_wait1()
{
    asm volatile("cp.async.wait_group 1;");
}

__device__ __forceinline__ uint32_t h2u(__half2 h)
{
    return *(uint32_t*)&h;
}

// ----------------------------------------------------------------------
// fp32 [K,N] -> fp16 [N,K] transpose (weights, once per launch)
// ----------------------------------------------------------------------
__global__ void __launch_bounds__(256) f2ht_kernel(
    const float* __restrict__ in, __half* __restrict__ out, int K, int N)
{
    __shared__ float tile[32][33];
    int bx = blockIdx.x * 32;   // N direction
    int by = blockIdx.y * 32;   // K direction
    int tx = threadIdx.x & 31;
    int ty = threadIdx.x >> 5;  // 0..7
    #pragma unroll
    for (int j = 0; j < 4; j++)
        tile[ty + 8*j][tx] = in[(size_t)(by + ty + 8*j)*N + bx + tx];
    __syncthreads();
    #pragma unroll
    for (int j = 0; j < 4; j++)
        out[(size_t)(bx + ty + 8*j)*K + by + tx] = __float2half(tile[tx][ty + 8*j]);
}

// ----------------------------------------------------------------------
// LayerNorm: fp32 in, fp16 out.
// ----------------------------------------------------------------------
__global__ void __launch_bounds__(256) ln_kernel(
    const float* __restrict__ x, const float* __restrict__ gw,
    const float* __restrict__ bw, __half* __restrict__ y)
{
    int row = blockIdx.x;
    int tid = threadIdx.x;
    float4 v = ((const float4*)(x + (size_t)row*DIM_))[tid];
    float s  = v.x + v.y + v.z + v.w;
    float ss = v.x*v.x + v.y*v.y + v.z*v.z + v.w*v.w;
    #pragma unroll
    for (int o = 16; o; o >>= 1) {
        s  += __shfl_xor_sync(0xffffffffu, s,  o);
        ss += __shfl_xor_sync(0xffffffffu, ss, o);
    }
    __shared__ float sm1[8];
    __shared__ float sm2[8];
    int w = tid >> 5;
    if ((tid & 31) == 0) { sm1[w] = s; sm2[w] = ss; }
    __syncthreads();
    s = 0.f; ss = 0.f;
    #pragma unroll
    for (int i = 0; i < 8; i++) { s += sm1[i]; ss += sm2[i]; }
    float mu  = s * (1.0f/1024.0f);
    float var = ss * (1.0f/1024.0f) - mu*mu;
    float r   = rsqrtf(var + 1e-5f);
    float4 g4 = ((const float4*)gw)[tid];
    float4 b4 = ((const float4*)bw)[tid];
    __half2 h0 = __floats2half2_rn((v.x - mu)*r*g4.x + b4.x, (v.y - mu)*r*g4.y + b4.y);
    __half2 h1 = __floats2half2_rn((v.z - mu)*r*g4.z + b4.z, (v.w - mu)*r*g4.w + b4.w);
    __half2* yp = (__half2*)(y + (size_t)row*DIM_);
    yp[tid*2]   = h0;
    yp[tid*2+1] = h1;
}

// ----------------------------------------------------------------------
// Tensor-core HGEMM v2: C[M,N] = A[M,K] @ Bt[N,K]^T + bias (+GELU) (+res)
// CTA tile 128x256, 8 warps (2 rows x 4 cols), warp tile 64x64.
// Padded 80B smem row stride: fully bank-conflict-free ldsm + stores.
// 3-stage cp.async pipeline, 1 CTA/SM.
// Both A and Bt are K-major fp16; B fragments use the validated
// 8-row x kg ldsm4 pattern (same as fattn K-tiles).
// ----------------------------------------------------------------------
#define BM  128
#define BN  256
#define BK  32
#define RSTR 80u                      // padded row stride in bytes
#define AST  (128u*RSTR)              // 10240 bytes per A stage
#define BST  (256u*RSTR)              // 20480 bytes per B stage
#define STG  (AST + BST)              // 30720 bytes per stage
#define TG_SMEM (3*30720)

template<int ACT, int RES, int OUT16>
__global__ void __launch_bounds__(256, 1) hgemm2_kernel(
    const __half* __restrict__ A, const __half* __restrict__ Bt,
    const float* __restrict__ bias, const float* __restrict__ res,
    void* __restrict__ Cout, int M, int N, int K)
{
    extern __shared__ char smem[];
    uint32_t sb = (uint32_t)__cvta_generic_to_shared(smem);

    int tid  = threadIdx.x;
    int lane = tid & 31;
    int warp = tid >> 5;
    int wm = (warp & 1) * 64;
    int wn = (warp >> 1) * 64;
    int row0 = blockIdx.y * BM;
    int col0 = blockIdx.x * BN;

    // cp.async mappings
    int am = tid >> 1;             // A row 0..127
    int ac = (tid & 1) * 2;        // A first chunk (of 4 16B groups)
    const __half* Ag = A  + (size_t)(row0 + am)*K + ac*8;
    const __half* Bg = Bt + (size_t)(col0 + tid)*K;
    uint32_t aOff0 = (uint32_t)am*RSTR + (uint32_t)(ac  )*16u;
    uint32_t aOff1 = (uint32_t)am*RSTR + (uint32_t)(ac+1)*16u;
    uint32_t bOff  = (uint32_t)tid*RSTR;

    float acc[4][8][4];
    #pragma unroll
    for (int i = 0; i < 4; i++)
        #pragma unroll
        for (int j = 0; j < 8; j++)
            #pragma unroll
            for (int t = 0; t < 4; t++)
                acc[i][j][t] = 0.f;

    int nIt = K / BK;

    // prologue: stages 0 and 1
    #pragma unroll
    for (int t = 0; t < 2; t++) {
        uint32_t s = sb + (uint32_t)t*STG;
        cpa16(s + aOff0, Ag + t*BK);
        cpa16(s + aOff1, Ag + t*BK + 8);
        uint32_t bs = s + AST + bOff;
        #pragma unroll
        for (int g = 0; g < 4; g++)
            cpa16(bs + g*16u, Bg + t*BK + g*8);
        cpa_commit();
    }

    for (int it = 0; it < nIt; it++) {
        if (it + 1 < nIt) cpa_wait1(); else cpa_wait0();
        __syncthreads();

        if (it + 2 < nIt) {
            uint32_t s = sb + (uint32_t)((it + 2) % 3)*STG;
            cpa16(s + aOff0, Ag + (it+2)*BK);
            cpa16(s + aOff1, Ag + (it+2)*BK + 8);
            uint32_t bs = s + AST + bOff;
            #pragma unroll
            for (int g = 0; g < 4; g++)
                cpa16(bs + g*16u, Bg + (size_t)(it+2)*BK + g*8);
            cpa_commit();
        }

        uint32_t abase = sb + (uint32_t)(it % 3)*STG;
        uint32_t bbase = abase + AST;

        // B fragments: one ldsm4 per 8-col n-tile, covers k0..31
        uint32_t bfr[8][4];
        #pragma unroll
        for (int nt = 0; nt < 8; nt++) {
            int r = wn + nt*8 + (lane & 7);
            uint32_t ad = bbase + (uint32_t)r*RSTR + (uint32_t)(lane >> 3)*16u;
            ldsm4(bfr[nt], ad);
        }

        #pragma unroll
        for (int ks = 0; ks < 2; ks++) {
            uint32_t afr[4][4];
            #pragma unroll
            for (int mt = 0; mt < 4; mt++) {
                int m  = wm + mt*16 + (lane & 15);
                int kg = ks*2 + (lane >> 4);
                uint32_t ad = abase + (uint32_t)m*RSTR + (uint32_t)kg*16u;
                ldsm4(afr[mt], ad);
            }
            #pragma unroll
            for (int mt = 0; mt < 4; mt++) {
                #pragma unroll
                for (int nt = 0; nt < 8; nt++) {
                    uint32_t bb[2];
                    bb[0] = bfr[nt][ks*2 + 0];
                    bb[1] = bfr[nt][ks*2 + 1];
                    mma16816(acc[mt][nt], afr[mt], bb);
                }
            }
        }
    }

    __syncthreads();

    // epilogue
    #pragma unroll
    for (int mt = 0; mt < 4; mt++) {
        #pragma unroll
        for (int hh = 0; hh < 2; hh++) {
            int r = row0 + wm + mt*16 + (lane >> 2) + hh*8;
            #pragma unroll
            for (int nt = 0; nt < 8; nt++) {
                int cc = col0 + wn + nt*8 + (lane & 3)*2;
                float v0 = acc[mt][nt][hh*2+0] + bias[cc];
                float v1 = acc[mt][nt][hh*2+1] + bias[cc+1];
                if (ACT == 1) {
                    v0 = 0.5f*v0*(1.0f + erff(v0*0.70710678f));
                    v1 = 0.5f*v1*(1.0f + erff(v1*0.70710678f));
                }
                if (RES == 1) {
                    float2 rr = *(const float2*)(res + (size_t)r*N + cc);
                    v0 += rr.x;
                    v1 += rr.y;
                }
                if (OUT16 == 1) {
                    __half* cp = (__half*)Cout + (size_t)r*N + cc;
                    *(__half2*)cp = __floats2half2_rn(v0, v1);
                } else {
                    float* cp = (float*)Cout + (size_t)r*N + cc;
                    *(float2*)cp = make_float2(v0, v1);
                }
            }
        }
    }
}

// ----------------------------------------------------------------------
// RoPE + split: fp16 qkv [NTOK,3*DIM] -> fp16 Q (prescaled 0.125), K, V
// ----------------------------------------------------------------------
__global__ void __launch_bounds__(256) rope_kernel(
    const __half* __restrict__ qkv,
    __half* __restrict__ Q, __half* __restrict__ K, __half* __restrict__ V)
{
    int idx = blockIdx.x * blockDim.x + threadIdx.x;
    int d = idx & 31;
    int h = (idx >> 5) & 15;
    int s = (idx >> 9) & 2047;
    int b = idx >> 20;
    int t = b*S_ + s;
    size_t base = (size_t)t*3072 + h*64 + d;
    float q1 = __half2float(qkv[base]);
    float q2 = __half2float(qkv[base + 32]);
    float k1 = __half2float(qkv[base + 1024]);
    float k2 = __half2float(qkv[base + 1056]);
    __half v1 = qkv[base + 2048];
    __half v2 = qkv[base + 2080];
    float inv = powf(10000.0f, -(float)d * (1.0f/32.0f));
    float ang = (float)s * inv;
    float sn, cs;
    sincosf(ang, &sn, &cs);
    size_t o = ((size_t)(b*H_ + h)*S_ + s)*64 + d;
    Q[o]      = __float2half((q1*cs - q2*sn) * 0.125f);
    Q[o + 32] = __float2half((q2*cs + q1*sn) * 0.125f);
    K[o]      = __float2half(k1*cs - k2*sn);
    K[o + 32] = __float2half(k2*cs + k1*sn);
    V[o]      = v1;
    V[o + 32] = v2;
}

// ----------------------------------------------------------------------
// Tensor-core flash attention (validated rounds 4-5).
// ----------------------------------------------------------------------
__global__ void __launch_bounds__(256) fattn_kernel(
    const __half* __restrict__ Q, const __half* __restrict__ K,
    const __half* __restrict__ V, const unsigned char* __restrict__ mask,
    __half* __restrict__ O)
{
    __shared__ __half sk[2][64*64];
    __shared__ __half sv[2][64*64];
    __shared__ float  smk[2][64];

    int tid  = threadIdx.x;
    int lane = tid & 31;
    int warp = tid >> 5;
    int bh = blockIdx.y;
    int b  = bh >> 4;
    int h  = bh & 15;
    int qt = blockIdx.x;

    const __half* Qb = Q + ((size_t)bh*S_ + (size_t)qt*128)*64;
    const __half* Kb = K + (size_t)bh*S_*64;
    const __half* Vb = V + (size_t)bh*S_*64;

    uint32_t skA = (uint32_t)__cvta_generic_to_shared(&sk[0][0]);
    uint32_t svA = (uint32_t)__cvta_generic_to_shared(&sv[0][0]);

    #pragma unroll
    for (int i = 0; i < 4; i++) {
        int c = tid + i*256;
        int r = c >> 3;
        int g = c & 7;
        uint32_t off = (uint32_t)(r*64 + ((g ^ (r & 7))*8)) * 2u;
        cpa16(skA + off, Qb + (size_t)r*64 + g*8);
    }
    cpa_commit();
    cpa_wait0();
    __syncthreads();

    uint32_t qf[4][4];
    {
        int row = warp*16 + (lane & 15);
        #pragma unroll
        for (int ks = 0; ks < 4; ks++) {
            int kg = ks*2 + (lane >> 4);
            uint32_t ad = skA + (uint32_t)(row*64 + ((kg ^ (row & 7))*8)) * 2u;
            ldsm4(qf[ks], ad);
        }
    }
    __syncthreads();

    float m1 = -3.0e38f, m2 = -3.0e38f, l1 = 0.f, l2 = 0.f;
    float acc[8][4];
    #pragma unroll
    for (int nt = 0; nt < 8; nt++)
        #pragma unroll
        for (int t = 0; t < 4; t++)
            acc[nt][t] = 0.f;

    {
        int r = tid >> 2;
        #pragma unroll
        for (int j = 0; j < 2; j++) {
            int g = (tid & 3)*2 + j;
            uint32_t off = (uint32_t)(r*64 + ((g ^ (r & 7))*8)) * 2u;
            cpa16(skA + off, Kb + (size_t)r*64 + g*8);
            cpa16(svA + off, Vb + (size_t)r*64 + g*8);
        }
        if (tid < 64)
            smk[0][tid] = mask[(size_t)b*S_ + tid] ? -3.0e38f : 0.0f;
    }
    cpa_commit();

    const int NKT = S_/64;
    for (int kt = 0; kt < NKT; kt++) {
        int buf = kt & 1;
        if (kt + 1 < NKT) {
            int nb = buf ^ 1;
            const __half* Kt = Kb + (size_t)(kt+1)*64*64;
            const __half* Vt = Vb + (size_t)(kt+1)*64*64;
            int r = tid >> 2;
            #pragma unroll
            for (int j = 0; j < 2; j++) {
                int g = (tid & 3)*2 + j;
                uint32_t off = (uint32_t)(nb*8192 + (r*64 + ((g ^ (r & 7))*8))*2);
                cpa16(skA + off, Kt + (size_t)r*64 + g*8);
                cpa16(svA + off, Vt + (size_t)r*64 + g*8);
            }
            if (tid < 64)
                smk[nb][tid] = mask[(size_t)b*S_ + (kt+1)*64 + tid] ? -3.0e38f : 0.0f;
            cpa_commit();
            cpa_wait1();
        } else {
            cpa_wait0();
        }
        __syncthreads();

        float sc[8][4];
        #pragma unroll
        for (int nt = 0; nt < 8; nt++) {
            sc[nt][0] = 0.f; sc[nt][1] = 0.f; sc[nt][2] = 0.f; sc[nt][3] = 0.f;
            int mrow = nt*8 + (lane & 7);
            uint32_t kb0[4], kb1[4];
            {
                int kg = (lane >> 3);
                ldsm4(kb0, skA + (uint32_t)(buf*8192 + (mrow*64 + ((kg ^ (mrow & 7))*8))*2));
            }
            {
                int kg = 4 + (lane >> 3);
                ldsm4(kb1, skA + (uint32_t)(buf*8192 + (mrow*64 + ((kg ^ (mrow & 7))*8))*2));
            }
            mma16816(sc[nt], qf[0], kb0 + 0);
            mma16816(sc[nt], qf[1], kb0 + 2);
            mma16816(sc[nt], qf[2], kb1 + 0);
            mma16816(sc[nt], qf[3], kb1 + 2);
        }

        float rmax1 = -3.0e38f, rmax2 = -3.0e38f;
        #pragma unroll
        for (int nt = 0; nt < 8; nt++) {
            int c0 = nt*8 + (lane & 3)*2;
            float k0 = smk[buf][c0];
            float k1 = smk[buf][c0 + 1];
            sc[nt][0] += k0; sc[nt][1] += k1;
            sc[nt][2] += k0; sc[nt][3] += k1;
            rmax1 = fmaxf(rmax1, fmaxf(sc[nt][0], sc[nt][1]));
            rmax2 = fmaxf(rmax2, fmaxf(sc[nt][2], sc[nt][3]));
        }
        rmax1 = fmaxf(rmax1, __shfl_xor_sync(0xffffffffu, rmax1, 1));
        rmax1 = fmaxf(rmax1, __shfl_xor_sync(0xffffffffu, rmax1, 2));
        rmax2 = fmaxf(rmax2, __shfl_xor_sync(0xffffffffu, rmax2, 1));
        rmax2 = fmaxf(rmax2, __shfl_xor_sync(0xffffffffu, rmax2, 2));

        float mn1 = fmaxf(m1, rmax1);
        float mn2 = fmaxf(m2, rmax2);
        float corr1 = __expf(m1 - mn1);
        float corr2 = __expf(m2 - mn2);
        float rs1 = 0.f, rs2 = 0.f;

        uint32_t pf[4][4];
        #pragma unroll
        for (int ktp = 0; ktp < 4; ktp++) {
            #pragma unroll
            for (int sub = 0; sub < 2; sub++) {
                int nt = ktp*2 + sub;
                float p0 = __expf(sc[nt][0] - mn1);
                float p1 = __expf(sc[nt][1] - mn1);
                float p2 = __expf(sc[nt][2] - mn2);
                float p3 = __expf(sc[nt][3] - mn2);
                rs1 += p0 + p1;
                rs2 += p2 + p3;
                pf[ktp][sub*2 + 0] = h2u(__floats2half2_rn(p0, p1));
                pf[ktp][sub*2 + 1] = h2u(__floats2half2_rn(p2, p3));
            }
        }
        rs1 += __shfl_xor_sync(0xffffffffu, rs1, 1);
        rs1 += __shfl_xor_sync(0xffffffffu, rs1, 2);
        rs2 += __shfl_xor_sync(0xffffffffu, rs2, 1);
        rs2 += __shfl_xor_sync(0xffffffffu, rs2, 2);

        m1 = mn1; m2 = mn2;
        l1 = l1*corr1 + rs1;
        l2 = l2*corr2 + rs2;
        #pragma unroll
        for (int nt = 0; nt < 8; nt++) {
            acc[nt][0] *= corr1; acc[nt][1] *= corr1;
            acc[nt][2] *= corr2; acc[nt][3] *= corr2;
        }

        #pragma unroll
        for (int nt = 0; nt < 8; nt++) {
            #pragma unroll
            for (int ktp = 0; ktp < 4; ktp++) {
                uint32_t vb[2];
                int r = ktp*16 + (lane & 15);
                int g = nt ^ (r & 7);
                ldsm2t(vb, svA + (uint32_t)(buf*8192 + (r*64 + g*8)*2));
                mma16816(acc[nt], pf[ktp], vb);
            }
        }
        __syncthreads();
    }

    float il1 = 1.0f / l1;
    float il2 = 1.0f / l2;
    int r1 = qt*128 + warp*16 + (lane >> 2);
    int r2 = r1 + 8;
    size_t row1 = ((size_t)b*S_ + r1)*DIM_ + h*64;
    size_t row2 = ((size_t)b*S_ + r2)*DIM_ + h*64;
    #pragma unroll
    for (int nt = 0; nt < 8; nt++) {
        int c = nt*8 + (lane & 3)*2;
        *(__half2*)(O + row1 + c) = __floats2half2_rn(acc[nt][0]*il1, acc[nt][1]*il1);
        *(__half2*)(O + row2 + c) = __floats2half2_rn(acc[nt][2]*il2, acc[nt][3]*il2);
    }
}

// ----------------------------------------------------------------------
// Orchestration
// ----------------------------------------------------------------------
extern "C" void kernel_launch(void* const* d_in, const int* in_sizes, int n_in,
                              void* d_out, int out_size)
{
    (void)in_sizes; (void)n_in; (void)out_size;
    const float*         x     = (const float*)d_in[0];
    const unsigned char* mask  = (const unsigned char*)d_in[1];
    const float*         qkv_w = (const float*)d_in[2];
    const float*         qkv_b = (const float*)d_in[3];
    const float*         out_w = (const float*)d_in[4];
    const float*         out_b = (const float*)d_in[5];
    const float*         ln1_g = (const float*)d_in[6];
    const float*         ln1_b = (const float*)d_in[7];
    const float*         ln2_g = (const float*)d_in[8];
    const float*         ln2_b = (const float*)d_in[9];
    const float*         w1    = (const float*)d_in[10];
    const float*         b1    = (const float*)d_in[11];
    const float*         w2    = (const float*)d_in[12];
    const float*         b2    = (const float*)d_in[13];
    float* out = (float*)d_out;

    __half* h16;
    __half* qkv16;
    __half* q16;
    __half* k16;
    __half* v16;
    __half* ctx16;
    __half* mid16;
    __half* qkvwT;
    __half* outwT;
    __half* w1T;
    __half* w2T;
    float* x1;
    cudaGetSymbolAddress((void**)&h16,   g_h16);
    cudaGetSymbolAddress((void**)&qkv16, g_qkv16);
    cudaGetSymbolAddress((void**)&q16,   g_q16);
    cudaGetSymbolAddress((void**)&k16,   g_k16);
    cudaGetSymbolAddress((void**)&v16,   g_v16);
    cudaGetSymbolAddress((void**)&ctx16, g_ctx16);
    cudaGetSymbolAddress((void**)&x1,    g_x1);
    cudaGetSymbolAddress((void**)&mid16, g_mid16);
    cudaGetSymbolAddress((void**)&qkvwT, g_qkvwT);
    cudaGetSymbolAddress((void**)&outwT, g_outwT);
    cudaGetSymbolAddress((void**)&w1T,   g_w1T);
    cudaGetSymbolAddress((void**)&w2T,   g_w2T);

    cudaFuncSetAttribute(hgemm2_kernel<0,0,1>,
        cudaFuncAttributeMaxDynamicSharedMemorySize, TG_SMEM);
    cudaFuncSetAttribute(hgemm2_kernel<0,1,0>,
        cudaFuncAttributeMaxDynamicSharedMemorySize, TG_SMEM);
    cudaFuncSetAttribute(hgemm2_kernel<1,0,1>,
        cudaFuncAttributeMaxDynamicSharedMemorySize, TG_SMEM);

    // weight transposes [K,N] -> [N,K] fp16
    f2ht_kernel<<<dim3(3*DIM_/32, DIM_/32), 256>>>(qkv_w, qkvwT, DIM_, 3*DIM_);
    f2ht_kernel<<<dim3(DIM_/32,   DIM_/32), 256>>>(out_w, outwT, DIM_, DIM_);
    f2ht_kernel<<<dim3(FFN_/32,   DIM_/32), 256>>>(w1,    w1T,   DIM_, FFN_);
    f2ht_kernel<<<dim3(DIM_/32,   FFN_/32), 256>>>(w2,    w2T,   FFN_, DIM_);

    ln_kernel<<<NTOK, 256>>>(x, ln1_g, ln1_b, h16);

    hgemm2_kernel<0,0,1><<<dim3(3*DIM_/BN, NTOK/BM), 256, TG_SMEM>>>(
        h16, qkvwT, qkv_b, (const float*)0, (void*)qkv16, NTOK, 3*DIM_, DIM_);

    rope_kernel<<<(NTOK*H_*32)/256, 256>>>(qkv16, q16, k16, v16);

    fattn_kernel<<<dim3(S_/128, B_*H_), 256>>>(q16, k16, v16, mask, ctx16);

    hgemm2_kernel<0,1,0><<<dim3(DIM_/BN, NTOK/BM), 256, TG_SMEM>>>(
        ctx16, outwT, out_b, x, (void*)x1, NTOK, DIM_, DIM_);

    ln_kernel<<<NTOK, 256>>>(x1, ln2_g, ln2_b, h16);

    hgemm2_kernel<1,0,1><<<dim3(FFN_/BN, NTOK/BM), 256, TG_SMEM>>>(
        h16, w1T, b1, (const float*)0, (void*)mid16, NTOK, FFN_, DIM_);

    hgemm2_kernel<0,1,0><<<dim3(DIM_/BN, NTOK/BM), 256, TG_SMEM>>>(
        mid16, w2T, b2, x1, (void*)out, NTOK, DIM_, FFN_);
}

// round 8
// speedup vs baseline: 1.5299x; 1.5299x over previous
#include <cuda_runtime.h>
#include <cuda_fp16.h>
#include <math.h>
#include <stdint.h>

#define B_    2
#define S_    2048
#define DIM_  1024
#define H_    16
#define HD_   64
#define FFN_  4096
#define NTOK  (B_*S_)

// ----------------------------------------------------------------------
// Scratch buffers (device globals; no allocation anywhere)
// ----------------------------------------------------------------------
__device__ __half g_h16[NTOK*DIM_];
__device__ __half g_qkv16[NTOK*3*DIM_];
__device__ __half g_q16[NTOK*DIM_];
__device__ __half g_k16[NTOK*DIM_];
__device__ __half g_v16[NTOK*DIM_];
__device__ __half g_ctx16[NTOK*DIM_];
__device__ float  g_x1[NTOK*DIM_];
__device__ __half g_mid16[NTOK*FFN_];
__device__ __half g_qkvw16[DIM_*3*DIM_];
__device__ __half g_outw16[DIM_*DIM_];
__device__ __half g_w116[DIM_*FFN_];
__device__ __half g_w216[FFN_*DIM_];

// ----------------------------------------------------------------------
// PTX helpers
// ----------------------------------------------------------------------
__device__ __forceinline__ void ldsm4(uint32_t* r, uint32_t addr)
{
    asm volatile("ldmatrix.sync.aligned.m8n8.x4.shared.b16 {%0,%1,%2,%3}, [%4];"
        : "=r"(r[0]), "=r"(r[1]), "=r"(r[2]), "=r"(r[3]) : "r"(addr));
}

__device__ __forceinline__ void ldsm4t(uint32_t* r, uint32_t addr)
{
    asm volatile("ldmatrix.sync.aligned.m8n8.x4.trans.shared.b16 {%0,%1,%2,%3}, [%4];"
        : "=r"(r[0]), "=r"(r[1]), "=r"(r[2]), "=r"(r[3]) : "r"(addr));
}

__device__ __forceinline__ void ldsm2t(uint32_t* r, uint32_t addr)
{
    asm volatile("ldmatrix.sync.aligned.m8n8.x2.trans.shared.b16 {%0,%1}, [%2];"
        : "=r"(r[0]), "=r"(r[1]) : "r"(addr));
}

__device__ __forceinline__ void mma16816(float* c, const uint32_t* a, const uint32_t* b)
{
    asm volatile("mma.sync.aligned.m16n8k16.row.col.f32.f16.f16.f32 "
        "{%0,%1,%2,%3}, {%4,%5,%6,%7}, {%8,%9}, {%0,%1,%2,%3};"
        : "+f"(c[0]), "+f"(c[1]), "+f"(c[2]), "+f"(c[3])
        : "r"(a[0]), "r"(a[1]), "r"(a[2]), "r"(a[3]), "r"(b[0]), "r"(b[1]));
}

__device__ __forceinline__ void cpa16(uint32_t dst, const void* src)
{
    asm volatile("cp.async.cg.shared.global [%0], [%1], 16;" :: "r"(dst), "l"(src));
}

__device__ __forceinline__ void cpa_commit()
{
    asm volatile("cp.async.commit_group;");
}

__device__ __forceinline__ void cpa_wait0()
{
    asm volatile("cp.async.wait_group 0;");
}

__device__ __forceinline__ void cpa_wait1()
{
    asm volatile("cp.async.wait_group 1;");
}

__device__ __forceinline__ uint32_t h2u(__half2 h)
{
    return *(uint32_t*)&h;
}

// ----------------------------------------------------------------------
// fp32 -> fp16 conversion, 4 float4 per thread
// ----------------------------------------------------------------------
__global__ void __launch_bounds__(256) f2h_kernel(
    const float4* __restrict__ s, __half2* __restrict__ d, int n4)
{
    int i0 = blockIdx.x * 1024 + threadIdx.x;
    #pragma unroll
    for (int u = 0; u < 4; u++) {
        int i = i0 + u*256;
        float4 v = s[i];
        d[2*i]   = __floats2half2_rn(v.x, v.y);
        d[2*i+1] = __floats2half2_rn(v.z, v.w);
    }
}

// ----------------------------------------------------------------------
// LayerNorm: fp32 in, fp16 out.
// ----------------------------------------------------------------------
__global__ void __launch_bounds__(256) ln_kernel(
    const float* __restrict__ x, const float* __restrict__ gw,
    const float* __restrict__ bw, __half* __restrict__ y)
{
    int row = blockIdx.x;
    int tid = threadIdx.x;
    float4 v = ((const float4*)(x + (size_t)row*DIM_))[tid];
    float s  = v.x + v.y + v.z + v.w;
    float ss = v.x*v.x + v.y*v.y + v.z*v.z + v.w*v.w;
    #pragma unroll
    for (int o = 16; o; o >>= 1) {
        s  += __shfl_xor_sync(0xffffffffu, s,  o);
        ss += __shfl_xor_sync(0xffffffffu, ss, o);
    }
    __shared__ float sm1[8];
    __shared__ float sm2[8];
    int w = tid >> 5;
    if ((tid & 31) == 0) { sm1[w] = s; sm2[w] = ss; }
    __syncthreads();
    s = 0.f; ss = 0.f;
    #pragma unroll
    for (int i = 0; i < 8; i++) { s += sm1[i]; ss += sm2[i]; }
    float mu  = s * (1.0f/1024.0f);
    float var = ss * (1.0f/1024.0f) - mu*mu;
    float r   = rsqrtf(var + 1e-5f);
    float4 g4 = ((const float4*)gw)[tid];
    float4 b4 = ((const float4*)bw)[tid];
    __half2 h0 = __floats2half2_rn((v.x - mu)*r*g4.x + b4.x, (v.y - mu)*r*g4.y + b4.y);
    __half2 h1 = __floats2half2_rn((v.z - mu)*r*g4.z + b4.z, (v.w - mu)*r*g4.w + b4.w);
    __half2* yp = (__half2*)(y + (size_t)row*DIM_);
    yp[tid*2]   = h0;
    yp[tid*2+1] = h1;
}

// ----------------------------------------------------------------------
// Tensor-core HGEMM v3: R5 config (128x128 tile, 64x32 warp tile,
// 2 CTA/SM) with BK=64 and 3-buffer cp.async pipeline.
// A tile: [128 rows][64 cols] = 128B rows, XOR-swizzled, conflict-free.
// B tile: [64 k-rows][128 n-cols] = 256B rows, R5 layout (validated).
// ----------------------------------------------------------------------
#define BM 128
#define BN 128
#define BK 64
#define ASTG 16384u
#define STG  32768u
#define TG_SMEM (3*32768)

template<int ACT, int RES, int OUT16>
__global__ void __launch_bounds__(256, 2) hgemm3_kernel(
    const __half* __restrict__ A, const __half* __restrict__ Bm,
    const float* __restrict__ bias, const float* __restrict__ res,
    void* __restrict__ Cout, int M, int N, int K)
{
    extern __shared__ char smem[];
    uint32_t sb = (uint32_t)__cvta_generic_to_shared(smem);

    int tid  = threadIdx.x;
    int lane = tid & 31;
    int warp = tid >> 5;
    int wm = (warp >> 2) * 64;
    int wn = (warp & 3) * 32;
    int row0 = blockIdx.y * BM;
    int col0 = blockIdx.x * BN;

    // load mappings: 1024 16B-chunks per operand stage, 4 per thread
    // A: chunk c -> row r=c>>3 (0..127), group g=c&7 ; phys group g^(r&7)
    // B: chunk c -> row r=c>>4 (0..63),  group g=c&15; phys group g^(r&7)
    float acc[4][4][4];
    #pragma unroll
    for (int i = 0; i < 4; i++)
        #pragma unroll
        for (int j = 0; j < 4; j++)
            #pragma unroll
            for (int t = 0; t < 4; t++)
                acc[i][j][t] = 0.f;

    int nIt = K / BK;

    // prologue: stages 0, 1
    #pragma unroll
    for (int t = 0; t < 2; t++) {
        uint32_t s = sb + (uint32_t)t*STG;
        #pragma unroll
        for (int i = 0; i < 4; i++) {
            int c = tid + i*256;
            int ra = c >> 3;
            int ga = c & 7;
            cpa16(s + (uint32_t)(ra*128 + ((ga ^ (ra & 7))*16)),
                  A + (size_t)(row0 + ra)*K + t*BK + ga*8);
            int rb = c >> 4;
            int gb = c & 15;
            cpa16(s + ASTG + (uint32_t)(rb*256 + ((gb ^ (rb & 7))*16)),
                  Bm + (size_t)(t*BK + rb)*N + col0 + gb*8);
        }
        cpa_commit();
    }

    for (int it = 0; it < nIt; it++) {
        if (it + 1 < nIt) cpa_wait1(); else cpa_wait0();
        __syncthreads();

        if (it + 2 < nIt) {
            int t = it + 2;
            uint32_t s = sb + (uint32_t)(t % 3)*STG;
            #pragma unroll
            for (int i = 0; i < 4; i++) {
                int c = tid + i*256;
                int ra = c >> 3;
                int ga = c & 7;
                cpa16(s + (uint32_t)(ra*128 + ((ga ^ (ra & 7))*16)),
                      A + (size_t)(row0 + ra)*K + t*BK + ga*8);
                int rb = c >> 4;
                int gb = c & 15;
                cpa16(s + ASTG + (uint32_t)(rb*256 + ((gb ^ (rb & 7))*16)),
                      Bm + (size_t)(t*BK + rb)*N + col0 + gb*8);
            }
            cpa_commit();
        }

        uint32_t abase = sb + (uint32_t)(it % 3)*STG;
        uint32_t bbase = abase + ASTG;

        #pragma unroll
        for (int ks = 0; ks < 4; ks++) {
            uint32_t afr[4][4];
            uint32_t bfr[2][4];
            #pragma unroll
            for (int mt = 0; mt < 4; mt++) {
                int m  = wm + mt*16 + (lane & 15);
                int kg = ks*2 + (lane >> 4);
                uint32_t ad = abase
                            + (uint32_t)(m*128 + ((kg ^ (m & 7))*16));
                ldsm4(afr[mt], ad);
            }
            #pragma unroll
            for (int p = 0; p < 2; p++) {
                int r = ks*16 + (lane & 15);
                int n = wn + p*16 + ((lane >> 4)*8);
                int g = (n >> 3) ^ (r & 7);
                uint32_t bd = bbase + (uint32_t)(r*256 + g*16);
                ldsm4t(bfr[p], bd);
            }
            #pragma unroll
            for (int mt = 0; mt < 4; mt++) {
                #pragma unroll
                for (int p = 0; p < 2; p++) {
                    mma16816(acc[mt][2*p],   afr[mt], bfr[p] + 0);
                    mma16816(acc[mt][2*p+1], afr[mt], bfr[p] + 2);
                }
            }
        }
    }

    __syncthreads();

    #pragma unroll
    for (int mt = 0; mt < 4; mt++) {
        #pragma unroll
        for (int hh = 0; hh < 2; hh++) {
            int r = row0 + wm + mt*16 + (lane >> 2) + hh*8;
            #pragma unroll
            for (int nt = 0; nt < 4; nt++) {
                int cc = col0 + wn + nt*8 + (lane & 3)*2;
                float v0 = acc[mt][nt][hh*2+0] + bias[cc];
                float v1 = acc[mt][nt][hh*2+1] + bias[cc+1];
                if (ACT == 1) {
                    v0 = 0.5f*v0*(1.0f + erff(v0*0.70710678f));
                    v1 = 0.5f*v1*(1.0f + erff(v1*0.70710678f));
                }
                if (RES == 1) {
                    float2 rr = *(const float2*)(res + (size_t)r*N + cc);
                    v0 += rr.x;
                    v1 += rr.y;
                }
                if (OUT16 == 1) {
                    __half* cp = (__half*)Cout + (size_t)r*N + cc;
                    *(__half2*)cp = __floats2half2_rn(v0, v1);
                } else {
                    float* cp = (float*)Cout + (size_t)r*N + cc;
                    *(float2*)cp = make_float2(v0, v1);
                }
            }
        }
    }
}

// ----------------------------------------------------------------------
// RoPE + split: fp16 qkv [NTOK,3*DIM] -> fp16 Q (prescaled 0.125), K, V
// ----------------------------------------------------------------------
__global__ void __launch_bounds__(256) rope_kernel(
    const __half* __restrict__ qkv,
    __half* __restrict__ Q, __half* __restrict__ K, __half* __restrict__ V)
{
    int idx = blockIdx.x * blockDim.x + threadIdx.x;
    int d = idx & 31;
    int h = (idx >> 5) & 15;
    int s = (idx >> 9) & 2047;
    int b = idx >> 20;
    int t = b*S_ + s;
    size_t base = (size_t)t*3072 + h*64 + d;
    float q1 = __half2float(qkv[base]);
    float q2 = __half2float(qkv[base + 32]);
    float k1 = __half2float(qkv[base + 1024]);
    float k2 = __half2float(qkv[base + 1056]);
    __half v1 = qkv[base + 2048];
    __half v2 = qkv[base + 2080];
    float inv = powf(10000.0f, -(float)d * (1.0f/32.0f));
    float ang = (float)s * inv;
    float sn, cs;
    sincosf(ang, &sn, &cs);
    size_t o = ((size_t)(b*H_ + h)*S_ + s)*64 + d;
    Q[o]      = __float2half((q1*cs - q2*sn) * 0.125f);
    Q[o + 32] = __float2half((q2*cs + q1*sn) * 0.125f);
    K[o]      = __float2half(k1*cs - k2*sn);
    K[o + 32] = __float2half(k2*cs + k1*sn);
    V[o]      = v1;
    V[o + 32] = v2;
}

// ----------------------------------------------------------------------
// Tensor-core flash attention (validated rounds 4-5).
// ----------------------------------------------------------------------
__global__ void __launch_bounds__(256) fattn_kernel(
    const __half* __restrict__ Q, const __half* __restrict__ K,
    const __half* __restrict__ V, const unsigned char* __restrict__ mask,
    __half* __restrict__ O)
{
    __shared__ __half sk[2][64*64];
    __shared__ __half sv[2][64*64];
    __shared__ float  smk[2][64];

    int tid  = threadIdx.x;
    int lane = tid & 31;
    int warp = tid >> 5;
    int bh = blockIdx.y;
    int b  = bh >> 4;
    int h  = bh & 15;
    int qt = blockIdx.x;

    const __half* Qb = Q + ((size_t)bh*S_ + (size_t)qt*128)*64;
    const __half* Kb = K + (size_t)bh*S_*64;
    const __half* Vb = V + (size_t)bh*S_*64;

    uint32_t skA = (uint32_t)__cvta_generic_to_shared(&sk[0][0]);
    uint32_t svA = (uint32_t)__cvta_generic_to_shared(&sv[0][0]);

    #pragma unroll
    for (int i = 0; i < 4; i++) {
        int c = tid + i*256;
        int r = c >> 3;
        int g = c & 7;
        uint32_t off = (uint32_t)(r*64 + ((g ^ (r & 7))*8)) * 2u;
        cpa16(skA + off, Qb + (size_t)r*64 + g*8);
    }
    cpa_commit();
    cpa_wait0();
    __syncthreads();

    uint32_t qf[4][4];
    {
        int row = warp*16 + (lane & 15);
        #pragma unroll
        for (int ks = 0; ks < 4; ks++) {
            int kg = ks*2 + (lane >> 4);
            uint32_t ad = skA + (uint32_t)(row*64 + ((kg ^ (row & 7))*8)) * 2u;
            ldsm4(qf[ks], ad);
        }
    }
    __syncthreads();

    float m1 = -3.0e38f, m2 = -3.0e38f, l1 = 0.f, l2 = 0.f;
    float acc[8][4];
    #pragma unroll
    for (int nt = 0; nt < 8; nt++)
        #pragma unroll
        for (int t = 0; t < 4; t++)
            acc[nt][t] = 0.f;

    {
        int r = tid >> 2;
        #pragma unroll
        for (int j = 0; j < 2; j++) {
            int g = (tid & 3)*2 + j;
            uint32_t off = (uint32_t)(r*64 + ((g ^ (r & 7))*8)) * 2u;
            cpa16(skA + off, Kb + (size_t)r*64 + g*8);
            cpa16(svA + off, Vb + (size_t)r*64 + g*8);
        }
        if (tid < 64)
            smk[0][tid] = mask[(size_t)b*S_ + tid] ? -3.0e38f : 0.0f;
    }
    cpa_commit();

    const int NKT = S_/64;
    for (int kt = 0; kt < NKT; kt++) {
        int buf = kt & 1;
        if (kt + 1 < NKT) {
            int nb = buf ^ 1;
            const __half* Kt = Kb + (size_t)(kt+1)*64*64;
            const __half* Vt = Vb + (size_t)(kt+1)*64*64;
            int r = tid >> 2;
            #pragma unroll
            for (int j = 0; j < 2; j++) {
                int g = (tid & 3)*2 + j;
                uint32_t off = (uint32_t)(nb*8192 + (r*64 + ((g ^ (r & 7))*8))*2);
                cpa16(skA + off, Kt + (size_t)r*64 + g*8);
                cpa16(svA + off, Vt + (size_t)r*64 + g*8);
            }
            if (tid < 64)
                smk[nb][tid] = mask[(size_t)b*S_ + (kt+1)*64 + tid] ? -3.0e38f : 0.0f;
            cpa_commit();
            cpa_wait1();
        } else {
            cpa_wait0();
        }
        __syncthreads();

        float sc[8][4];
        #pragma unroll
        for (int nt = 0; nt < 8; nt++) {
            sc[nt][0] = 0.f; sc[nt][1] = 0.f; sc[nt][2] = 0.f; sc[nt][3] = 0.f;
            int mrow = nt*8 + (lane & 7);
            uint32_t kb0[4], kb1[4];
            {
                int kg = (lane >> 3);
                ldsm4(kb0, skA + (uint32_t)(buf*8192 + (mrow*64 + ((kg ^ (mrow & 7))*8))*2));
            }
            {
                int kg = 4 + (lane >> 3);
                ldsm4(kb1, skA + (uint32_t)(buf*8192 + (mrow*64 + ((kg ^ (mrow & 7))*8))*2));
            }
            mma16816(sc[nt], qf[0], kb0 + 0);
            mma16816(sc[nt], qf[1], kb0 + 2);
            mma16816(sc[nt], qf[2], kb1 + 0);
            mma16816(sc[nt], qf[3], kb1 + 2);
        }

        float rmax1 = -3.0e38f, rmax2 = -3.0e38f;
        #pragma unroll
        for (int nt = 0; nt < 8; nt++) {
            int c0 = nt*8 + (lane & 3)*2;
            float k0 = smk[buf][c0];
            float k1 = smk[buf][c0 + 1];
            sc[nt][0] += k0; sc[nt][1] += k1;
            sc[nt][2] += k0; sc[nt][3] += k1;
            rmax1 = fmaxf(rmax1, fmaxf(sc[nt][0], sc[nt][1]));
            rmax2 = fmaxf(rmax2, fmaxf(sc[nt][2], sc[nt][3]));
        }
        rmax1 = fmaxf(rmax1, __shfl_xor_sync(0xffffffffu, rmax1, 1));
        rmax1 = fmaxf(rmax1, __shfl_xor_sync(0xffffffffu, rmax1, 2));
        rmax2 = fmaxf(rmax2, __shfl_xor_sync(0xffffffffu, rmax2, 1));
        rmax2 = fmaxf(rmax2, __shfl_xor_sync(0xffffffffu, rmax2, 2));

        float mn1 = fmaxf(m1, rmax1);
        float mn2 = fmaxf(m2, rmax2);
        float corr1 = __expf(m1 - mn1);
        float corr2 = __expf(m2 - mn2);
        float rs1 = 0.f, rs2 = 0.f;

        uint32_t pf[4][4];
        #pragma unroll
        for (int ktp = 0; ktp < 4; ktp++) {
            #pragma unroll
            for (int sub = 0; sub < 2; sub++) {
                int nt = ktp*2 + sub;
                float p0 = __expf(sc[nt][0] - mn1);
                float p1 = __expf(sc[nt][1] - mn1);
                float p2 = __expf(sc[nt][2] - mn2);
                float p3 = __expf(sc[nt][3] - mn2);
                rs1 += p0 + p1;
                rs2 += p2 + p3;
                pf[ktp][sub*2 + 0] = h2u(__floats2half2_rn(p0, p1));
                pf[ktp][sub*2 + 1] = h2u(__floats2half2_rn(p2, p3));
            }
        }
        rs1 += __shfl_xor_sync(0xffffffffu, rs1, 1);
        rs1 += __shfl_xor_sync(0xffffffffu, rs1, 2);
        rs2 += __shfl_xor_sync(0xffffffffu, rs2, 1);
        rs2 += __shfl_xor_sync(0xffffffffu, rs2, 2);

        m1 = mn1; m2 = mn2;
        l1 = l1*corr1 + rs1;
        l2 = l2*corr2 + rs2;
        #pragma unroll
        for (int nt = 0; nt < 8; nt++) {
            acc[nt][0] *= corr1; acc[nt][1] *= corr1;
            acc[nt][2] *= corr2; acc[nt][3] *= corr2;
        }

        #pragma unroll
        for (int nt = 0; nt < 8; nt++) {
            #pragma unroll
            for (int ktp = 0; ktp < 4; ktp++) {
                uint32_t vb[2];
                int r = ktp*16 + (lane & 15);
                int g = nt ^ (r & 7);
                ldsm2t(vb, svA + (uint32_t)(buf*8192 + (r*64 + g*8)*2));
                mma16816(acc[nt], pf[ktp], vb);
            }
        }
        __syncthreads();
    }

    float il1 = 1.0f / l1;
    float il2 = 1.0f / l2;
    int r1 = qt*128 + warp*16 + (lane >> 2);
    int r2 = r1 + 8;
    size_t row1 = ((size_t)b*S_ + r1)*DIM_ + h*64;
    size_t row2 = ((size_t)b*S_ + r2)*DIM_ + h*64;
    #pragma unroll
    for (int nt = 0; nt < 8; nt++) {
        int c = nt*8 + (lane & 3)*2;
        *(__half2*)(O + row1 + c) = __floats2half2_rn(acc[nt][0]*il1, acc[nt][1]*il1);
        *(__half2*)(O + row2 + c) = __floats2half2_rn(acc[nt][2]*il2, acc[nt][3]*il2);
    }
}

// ----------------------------------------------------------------------
// Orchestration
// ----------------------------------------------------------------------
extern "C" void kernel_launch(void* const* d_in, const int* in_sizes, int n_in,
                              void* d_out, int out_size)
{
    (void)in_sizes; (void)n_in; (void)out_size;
    const float*         x     = (const float*)d_in[0];
    const unsigned char* mask  = (const unsigned char*)d_in[1];
    const float*         qkv_w = (const float*)d_in[2];
    const float*         qkv_b = (const float*)d_in[3];
    const float*         out_w = (const float*)d_in[4];
    const float*         out_b = (const float*)d_in[5];
    const float*         ln1_g = (const float*)d_in[6];
    const float*         ln1_b = (const float*)d_in[7];
    const float*         ln2_g = (const float*)d_in[8];
    const float*         ln2_b = (const float*)d_in[9];
    const float*         w1    = (const float*)d_in[10];
    const float*         b1    = (const float*)d_in[11];
    const float*         w2    = (const float*)d_in[12];
    const float*         b2    = (const float*)d_in[13];
    float* out = (float*)d_out;

    __half* h16;
    __half* qkv16;
    __half* q16;
    __half* k16;
    __half* v16;
    __half* ctx16;
    __half* mid16;
    __half* qkvw16;
    __half* outw16;
    __half* w116;
    __half* w216;
    float* x1;
    cudaGetSymbolAddress((void**)&h16,    g_h16);
    cudaGetSymbolAddress((void**)&qkv16,  g_qkv16);
    cudaGetSymbolAddress((void**)&q16,    g_q16);
    cudaGetSymbolAddress((void**)&k16,    g_k16);
    cudaGetSymbolAddress((void**)&v16,    g_v16);
    cudaGetSymbolAddress((void**)&ctx16,  g_ctx16);
    cudaGetSymbolAddress((void**)&x1,     g_x1);
    cudaGetSymbolAddress((void**)&mid16,  g_mid16);
    cudaGetSymbolAddress((void**)&qkvw16, g_qkvw16);
    cudaGetSymbolAddress((void**)&outw16, g_outw16);
    cudaGetSymbolAddress((void**)&w116,   g_w116);
    cudaGetSymbolAddress((void**)&w216,   g_w216);

    cudaFuncSetAttribute(hgemm3_kernel<0,0,1>,
        cudaFuncAttributeMaxDynamicSharedMemorySize, TG_SMEM);
    cudaFuncSetAttribute(hgemm3_kernel<0,1,0>,
        cudaFuncAttributeMaxDynamicSharedMemorySize, TG_SMEM);
    cudaFuncSetAttribute(hgemm3_kernel<1,0,1>,
        cudaFuncAttributeMaxDynamicSharedMemorySize, TG_SMEM);

    f2h_kernel<<<DIM_*3*DIM_/4/1024, 256>>>((const float4*)qkv_w, (__half2*)qkvw16, DIM_*3*DIM_/4);
    f2h_kernel<<<DIM_*DIM_/4/1024,   256>>>((const float4*)out_w, (__half2*)outw16, DIM_*DIM_/4);
    f2h_kernel<<<DIM_*FFN_/4/1024,   256>>>((const float4*)w1,    (__half2*)w116,   DIM_*FFN_/4);
    f2h_kernel<<<FFN_*DIM_/4/1024,   256>>>((const float4*)w2,    (__half2*)w216,   FFN_*DIM_/4);

    ln_kernel<<<NTOK, 256>>>(x, ln1_g, ln1_b, h16);

    hgemm3_kernel<0,0,1><<<dim3(3*DIM_/BN, NTOK/BM), 256, TG_SMEM>>>(
        h16, qkvw16, qkv_b, (const float*)0, (void*)qkv16, NTOK, 3*DIM_, DIM_);

    rope_kernel<<<(NTOK*H_*32)/256, 256>>>(qkv16, q16, k16, v16);

    fattn_kernel<<<dim3(S_/128, B_*H_), 256>>>(q16, k16, v16, mask, ctx16);

    hgemm3_kernel<0,1,0><<<dim3(DIM_/BN, NTOK/BM), 256, TG_SMEM>>>(
        ctx16, outw16, out_b, x, (void*)x1, NTOK, DIM_, DIM_);

    ln_kernel<<<NTOK, 256>>>(x1, ln2_g, ln2_b, h16);

    hgemm3_kernel<1,0,1><<<dim3(FFN_/BN, NTOK/BM), 256, TG_SMEM>>>(
        h16, w116, b1, (const float*)0, (void*)mid16, NTOK, FFN_, DIM_);

    hgemm3_kernel<0,1,0><<<dim3(DIM_/BN, NTOK/BM), 256, TG_SMEM>>>(
        mid16, w216, b2, x1, (void*)out, NTOK, DIM_, FFN_);
}